// round 1
// baseline (speedup 1.0000x reference)
#include <cuda_runtime.h>
#include <cuda_bf16.h>

// Problem: Zim_67430986547716
// boxes: (256,4) f32, point_coords: (256,32,2) f32
// outputs concatenated: bbox_mask (256,64,64) f32 then point_mask (256,64,64) f32
//
// Strategy: one block per box (256 blocks, 256 threads).
//  - Gaussian is separable: exp(-(di^2+dj^2)/882) = exp(-di^2/882)*exp(-dj^2/882).
//    Precompute gys[32][64] and gxs[32][64] into shared (4096 MUFU/block),
//    fold point-validity in as zeros.
//  - Each thread owns 16 contiguous pixels of one row: register max-accumulators,
//    inner loop = 32 points x (1 LDS.32 row factor + 4 LDS.128 col factors +
//    16 mul + 16 fmax). Vectorized float4 stores for both outputs.

#define MASK_N 64
#define NPTS   32
#define INV_STRIDE (1.0f / 16.0f)
#define INV_2SIG2  (1.0f / 882.0f)   // 2*21*21

__global__ __launch_bounds__(256, 4)
void zim_masks_kernel(const float* __restrict__ boxes,
                      const float* __restrict__ pts,
                      float* __restrict__ bbox_out,
                      float* __restrict__ point_out)
{
    __shared__ float gxs[NPTS * MASK_N];   // gxs[p*64 + j] = valid ? exp(-(j-px)^2/882) : 0
    __shared__ float gys[NPTS * MASK_N];   // gys[p*64 + i] = valid ? exp(-(i-py)^2/882) : 0

    const int b   = blockIdx.x;
    const int tid = threadIdx.x;

    // ---- bbox bounds (redundant per-thread: 4 loads, hits L1/L2 broadcast) ----
    const float x0 = boxes[b * 4 + 0];
    const float y0 = boxes[b * 4 + 1];
    const float x1 = boxes[b * 4 + 2];
    const float y1 = boxes[b * 4 + 3];
    const float xminf = fminf(x0, x1), xmaxf = fmaxf(x0, x1);
    const float yminf = fminf(y0, y1), ymaxf = fmaxf(y0, y1);
    // division by 16 is exact in fp32 -> mul by 1/16 identical
    const int xmin_i = max((int)floorf(xminf * INV_STRIDE), 0);
    const int ymin_i = max((int)floorf(yminf * INV_STRIDE), 0);
    const int xmax_i = min((int)floorf(xmaxf * INV_STRIDE) + 1, MASK_N);
    const int ymax_i = min((int)floorf(ymaxf * INV_STRIDE) + 1, MASK_N);

    // ---- build separable Gaussian tables: 2048 entries, 8 per thread ----
    #pragma unroll
    for (int idx = tid; idx < NPTS * MASK_N; idx += 256) {
        const int p = idx >> 6;        // point index
        const int g = idx & 63;        // grid coordinate
        const float x = pts[(b * NPTS + p) * 2 + 0];
        const float y = pts[(b * NPTS + p) * 2 + 1];
        const int px = (int)floorf(x * INV_STRIDE);
        const int py = (int)floorf(y * INV_STRIDE);
        const bool valid = (px >= 0) & (py >= 0) & (px < MASK_N) & (py < MASK_N);
        const float dx = (float)(g - px);
        const float dy = (float)(g - py);
        gxs[idx] = valid ? __expf(-dx * dx * INV_2SIG2) : 0.0f;
        gys[idx] = valid ? __expf(-dy * dy * INV_2SIG2) : 0.0f;
    }
    __syncthreads();

    // ---- each thread: row i, 16 contiguous columns starting at j0 ----
    const int i  = tid >> 2;           // 0..63
    const int j0 = (tid & 3) << 4;     // 0,16,32,48

    float m[16];
    #pragma unroll
    for (int k = 0; k < 16; k++) m[k] = 0.0f;

    #pragma unroll 4
    for (int p = 0; p < NPTS; p++) {
        const float ry = gys[p * MASK_N + i];
        const float4* gx4 = reinterpret_cast<const float4*>(&gxs[p * MASK_N + j0]);
        #pragma unroll
        for (int q = 0; q < 4; q++) {
            const float4 g = gx4[q];
            m[q * 4 + 0] = fmaxf(m[q * 4 + 0], ry * g.x);
            m[q * 4 + 1] = fmaxf(m[q * 4 + 1], ry * g.y);
            m[q * 4 + 2] = fmaxf(m[q * 4 + 2], ry * g.z);
            m[q * 4 + 3] = fmaxf(m[q * 4 + 3], ry * g.w);
        }
    }

    // ---- stores: 4x float4 per output ----
    const size_t base = (size_t)b * (MASK_N * MASK_N) + (size_t)i * MASK_N + j0;
    float4* pout = reinterpret_cast<float4*>(point_out + base);
    float4* bout = reinterpret_cast<float4*>(bbox_out + base);

    const bool inY = (i >= ymin_i) & (i < ymax_i);
    #pragma unroll
    for (int q = 0; q < 4; q++) {
        pout[q] = make_float4(m[q * 4 + 0], m[q * 4 + 1], m[q * 4 + 2], m[q * 4 + 3]);
        const int jq = j0 + q * 4;
        float4 bv;
        bv.x = (inY & (jq + 0 >= xmin_i) & (jq + 0 < xmax_i)) ? 1.0f : 0.0f;
        bv.y = (inY & (jq + 1 >= xmin_i) & (jq + 1 < xmax_i)) ? 1.0f : 0.0f;
        bv.z = (inY & (jq + 2 >= xmin_i) & (jq + 2 < xmax_i)) ? 1.0f : 0.0f;
        bv.w = (inY & (jq + 3 >= xmin_i) & (jq + 3 < xmax_i)) ? 1.0f : 0.0f;
        bout[q] = bv;
    }
}

extern "C" void kernel_launch(void* const* d_in, const int* in_sizes, int n_in,
                              void* d_out, int out_size) {
    const float* boxes = (const float*)d_in[0];       // 256*4
    const float* pts   = (const float*)d_in[1];       // 256*32*2
    float* out = (float*)d_out;                       // 2 * 256*64*64
    const int B = in_sizes[0] / 4;                    // 256
    float* bbox_out  = out;
    float* point_out = out + (size_t)B * MASK_N * MASK_N;
    zim_masks_kernel<<<B, 256>>>(boxes, pts, bbox_out, point_out);
}

// round 2
// speedup vs baseline: 1.5802x; 1.5802x over previous
#include <cuda_runtime.h>
#include <cuda_bf16.h>

// Zim_67430986547716 — bbox mask + separable-Gaussian point mask.
// R2: fix occupancy (grid 256 -> 512) and raise per-warp ILP with a
// 2-row x 4-col register tile per thread (16 math ops per 2 LDS per point).

#define MASK_N 64
#define NPTS   32
#define ROWS_PER_BLOCK 32
#define INV_STRIDE (1.0f / 16.0f)
#define INV_2SIG2  (1.0f / 882.0f)   // 2*21*21

__global__ __launch_bounds__(256, 4)
void zim_masks_kernel(const float* __restrict__ boxes,
                      const float* __restrict__ pts,
                      float* __restrict__ bbox_out,
                      float* __restrict__ point_out)
{
    __shared__ float gxs[NPTS * MASK_N];          // 8KB: [p][j] col Gaussian (valid folded)
    __shared__ float gys[NPTS * ROWS_PER_BLOCK];  // 4KB: [p][local_i] row Gaussian
    __shared__ float spx[NPTS], spy[NPTS], sval[NPTS];

    const int b      = blockIdx.x;
    const int sub    = blockIdx.y;            // 0 or 1: which 32-row half
    const int i_base = sub * ROWS_PER_BLOCK;
    const int tid    = threadIdx.x;

    // ---- stage point centers + validity (one warp) ----
    if (tid < NPTS) {
        const float x = pts[(b * NPTS + tid) * 2 + 0];
        const float y = pts[(b * NPTS + tid) * 2 + 1];
        const float pxf = floorf(x * INV_STRIDE);
        const float pyf = floorf(y * INV_STRIDE);
        const bool valid = (pxf >= 0.0f) & (pyf >= 0.0f) &
                           (pxf < (float)MASK_N) & (pyf < (float)MASK_N);
        spx[tid] = pxf;
        spy[tid] = pyf;
        sval[tid] = valid ? 1.0f : 0.0f;
    }

    // ---- bbox bounds (uniform, cheap; L1 broadcast) ----
    const float x0 = boxes[b * 4 + 0];
    const float y0 = boxes[b * 4 + 1];
    const float x1 = boxes[b * 4 + 2];
    const float y1 = boxes[b * 4 + 3];
    const int xmin_i = max((int)floorf(fminf(x0, x1) * INV_STRIDE), 0);
    const int ymin_i = max((int)floorf(fminf(y0, y1) * INV_STRIDE), 0);
    const int xmax_i = min((int)floorf(fmaxf(x0, x1) * INV_STRIDE) + 1, MASK_N);
    const int ymax_i = min((int)floorf(fmaxf(y0, y1) * INV_STRIDE) + 1, MASK_N);

    __syncthreads();

    // ---- build Gaussian tables from staged centers ----
    #pragma unroll
    for (int idx = tid; idx < NPTS * MASK_N; idx += 256) {      // 8 iters
        const int p = idx >> 6;
        const float dx = (float)(idx & 63) - spx[p];
        gxs[idx] = sval[p] * __expf(-dx * dx * INV_2SIG2);
    }
    #pragma unroll
    for (int idx = tid; idx < NPTS * ROWS_PER_BLOCK; idx += 256) {  // 4 iters
        const int p = idx >> 5;
        const float dy = (float)(i_base + (idx & 31)) - spy[p];
        gys[idx] = sval[p] * __expf(-dy * dy * INV_2SIG2);
    }
    __syncthreads();

    // ---- per-thread tile: 2 rows x 4 cols ----
    const int rg = tid >> 4;            // 0..15 -> local rows rg*2, rg*2+1
    const int il = rg << 1;
    const int c  = (tid & 15) << 2;     // col start: 0,4,...,60

    float m0x = 0.f, m0y = 0.f, m0z = 0.f, m0w = 0.f;
    float m1x = 0.f, m1y = 0.f, m1z = 0.f, m1w = 0.f;

    #pragma unroll 8
    for (int p = 0; p < NPTS; p++) {
        const float2 ry = *reinterpret_cast<const float2*>(&gys[p * ROWS_PER_BLOCK + il]);
        const float4 g  = *reinterpret_cast<const float4*>(&gxs[p * MASK_N + c]);
        m0x = fmaxf(m0x, ry.x * g.x);
        m0y = fmaxf(m0y, ry.x * g.y);
        m0z = fmaxf(m0z, ry.x * g.z);
        m0w = fmaxf(m0w, ry.x * g.w);
        m1x = fmaxf(m1x, ry.y * g.x);
        m1y = fmaxf(m1y, ry.y * g.y);
        m1z = fmaxf(m1z, ry.y * g.z);
        m1w = fmaxf(m1w, ry.y * g.w);
    }

    // ---- stores ----
    const int i0 = i_base + il;
    const size_t base0 = (size_t)b * (MASK_N * MASK_N) + (size_t)i0 * MASK_N + c;

    *reinterpret_cast<float4*>(point_out + base0)          = make_float4(m0x, m0y, m0z, m0w);
    *reinterpret_cast<float4*>(point_out + base0 + MASK_N) = make_float4(m1x, m1y, m1z, m1w);

    const bool inX0 = (c + 0 >= xmin_i) & (c + 0 < xmax_i);
    const bool inX1 = (c + 1 >= xmin_i) & (c + 1 < xmax_i);
    const bool inX2 = (c + 2 >= xmin_i) & (c + 2 < xmax_i);
    const bool inX3 = (c + 3 >= xmin_i) & (c + 3 < xmax_i);
    const bool inY0 = (i0 >= ymin_i) & (i0 < ymax_i);
    const bool inY1 = (i0 + 1 >= ymin_i) & (i0 + 1 < ymax_i);

    *reinterpret_cast<float4*>(bbox_out + base0) =
        make_float4((inY0 & inX0) ? 1.f : 0.f, (inY0 & inX1) ? 1.f : 0.f,
                    (inY0 & inX2) ? 1.f : 0.f, (inY0 & inX3) ? 1.f : 0.f);
    *reinterpret_cast<float4*>(bbox_out + base0 + MASK_N) =
        make_float4((inY1 & inX0) ? 1.f : 0.f, (inY1 & inX1) ? 1.f : 0.f,
                    (inY1 & inX2) ? 1.f : 0.f, (inY1 & inX3) ? 1.f : 0.f);
}

extern "C" void kernel_launch(void* const* d_in, const int* in_sizes, int n_in,
                              void* d_out, int out_size) {
    const float* boxes = (const float*)d_in[0];   // 256*4
    const float* pts   = (const float*)d_in[1];   // 256*32*2
    float* out = (float*)d_out;                   // 2 * 256*64*64
    const int B = in_sizes[0] / 4;                // 256
    float* bbox_out  = out;
    float* point_out = out + (size_t)B * MASK_N * MASK_N;
    dim3 grid(B, 2);
    zim_masks_kernel<<<grid, 256>>>(boxes, pts, bbox_out, point_out);
}

// round 3
// speedup vs baseline: 1.6131x; 1.0208x over previous
#include <cuda_runtime.h>
#include <cuda_bf16.h>

// Zim_67430986547716 — bbox mask + separable-Gaussian point mask.
// R3: the R2 kernel was MUFU-bound (3072 __expf per block in the table build,
// 1.57M total -> ~21K cyc/SMSP at rt=8). Gaussian distances are integers in
// [0,127], so replace per-entry exp with a 128-entry shared LUT (128 MUFU per
// block). Main loop (FMUL+FMNMX dual-pipe) becomes the bottleneck (~1.8us floor).

#define MASK_N 64
#define NPTS   32
#define ROWS_PER_BLOCK 32
#define INV_STRIDE (1.0f / 16.0f)
#define INV_2SIG2  (1.0f / 882.0f)   // 2*21*21

__global__ __launch_bounds__(256, 4)
void zim_masks_kernel(const float* __restrict__ boxes,
                      const float* __restrict__ pts,
                      float* __restrict__ bbox_out,
                      float* __restrict__ point_out)
{
    __shared__ float gxs[NPTS * MASK_N];          // 8KB: [p][j] col Gaussian (valid folded)
    __shared__ float gys[NPTS * ROWS_PER_BLOCK];  // 4KB: [p][local_i] row Gaussian
    __shared__ float etab[128];                   // exp(-k^2/882), k = |integer distance|
    __shared__ int   spx[NPTS], spy[NPTS];
    __shared__ float sval[NPTS];

    const int b      = blockIdx.x;
    const int sub    = blockIdx.y;            // 0 or 1: which 32-row half
    const int i_base = sub * ROWS_PER_BLOCK;
    const int tid    = threadIdx.x;

    // ---- LUT: only 128 MUFU per block ----
    if (tid < 128) {
        const float d = (float)tid;
        etab[tid] = __expf(-d * d * INV_2SIG2);
    }

    // ---- stage point centers + validity (one warp) ----
    if (tid >= 128 && tid < 128 + NPTS) {
        const int p = tid - 128;
        const float x = pts[(b * NPTS + p) * 2 + 0];
        const float y = pts[(b * NPTS + p) * 2 + 1];
        const int px = (int)floorf(x * INV_STRIDE);
        const int py = (int)floorf(y * INV_STRIDE);
        const bool valid = (px >= 0) & (py >= 0) & (px < MASK_N) & (py < MASK_N);
        spx[p] = px;
        spy[p] = py;
        sval[p] = valid ? 1.0f : 0.0f;
    }

    // ---- bbox bounds (uniform; L1 broadcast) ----
    const float x0 = boxes[b * 4 + 0];
    const float y0 = boxes[b * 4 + 1];
    const float x1 = boxes[b * 4 + 2];
    const float y1 = boxes[b * 4 + 3];
    const int xmin_i = max((int)floorf(fminf(x0, x1) * INV_STRIDE), 0);
    const int ymin_i = max((int)floorf(fminf(y0, y1) * INV_STRIDE), 0);
    const int xmax_i = min((int)floorf(fmaxf(x0, x1) * INV_STRIDE) + 1, MASK_N);
    const int ymax_i = min((int)floorf(fmaxf(y0, y1) * INV_STRIDE) + 1, MASK_N);

    __syncthreads();

    // ---- build Gaussian tables via LUT (int ALU + LDS only) ----
    #pragma unroll
    for (int idx = tid; idx < NPTS * MASK_N; idx += 256) {      // 8 iters
        const int p = idx >> 6;
        int d = (idx & 63) - spx[p];
        d = abs(d);
        d = min(d, 127);
        gxs[idx] = sval[p] * etab[d];
    }
    #pragma unroll
    for (int idx = tid; idx < NPTS * ROWS_PER_BLOCK; idx += 256) {  // 4 iters
        const int p = idx >> 5;
        int d = i_base + (idx & 31) - spy[p];
        d = abs(d);
        d = min(d, 127);
        gys[idx] = sval[p] * etab[d];
    }
    __syncthreads();

    // ---- per-thread tile: 2 rows x 4 cols ----
    const int rg = tid >> 4;            // 0..15 -> local rows rg*2, rg*2+1
    const int il = rg << 1;
    const int c  = (tid & 15) << 2;     // col start: 0,4,...,60

    float m0x = 0.f, m0y = 0.f, m0z = 0.f, m0w = 0.f;
    float m1x = 0.f, m1y = 0.f, m1z = 0.f, m1w = 0.f;

    #pragma unroll 8
    for (int p = 0; p < NPTS; p++) {
        const float2 ry = *reinterpret_cast<const float2*>(&gys[p * ROWS_PER_BLOCK + il]);
        const float4 g  = *reinterpret_cast<const float4*>(&gxs[p * MASK_N + c]);
        m0x = fmaxf(m0x, ry.x * g.x);
        m0y = fmaxf(m0y, ry.x * g.y);
        m0z = fmaxf(m0z, ry.x * g.z);
        m0w = fmaxf(m0w, ry.x * g.w);
        m1x = fmaxf(m1x, ry.y * g.x);
        m1y = fmaxf(m1y, ry.y * g.y);
        m1z = fmaxf(m1z, ry.y * g.z);
        m1w = fmaxf(m1w, ry.y * g.w);
    }

    // ---- stores ----
    const int i0 = i_base + il;
    const size_t base0 = (size_t)b * (MASK_N * MASK_N) + (size_t)i0 * MASK_N + c;

    *reinterpret_cast<float4*>(point_out + base0)          = make_float4(m0x, m0y, m0z, m0w);
    *reinterpret_cast<float4*>(point_out + base0 + MASK_N) = make_float4(m1x, m1y, m1z, m1w);

    const bool inX0 = (c + 0 >= xmin_i) & (c + 0 < xmax_i);
    const bool inX1 = (c + 1 >= xmin_i) & (c + 1 < xmax_i);
    const bool inX2 = (c + 2 >= xmin_i) & (c + 2 < xmax_i);
    const bool inX3 = (c + 3 >= xmin_i) & (c + 3 < xmax_i);
    const bool inY0 = (i0 >= ymin_i) & (i0 < ymax_i);
    const bool inY1 = (i0 + 1 >= ymin_i) & (i0 + 1 < ymax_i);

    *reinterpret_cast<float4*>(bbox_out + base0) =
        make_float4((inY0 & inX0) ? 1.f : 0.f, (inY0 & inX1) ? 1.f : 0.f,
                    (inY0 & inX2) ? 1.f : 0.f, (inY0 & inX3) ? 1.f : 0.f);
    *reinterpret_cast<float4*>(bbox_out + base0 + MASK_N) =
        make_float4((inY1 & inX0) ? 1.f : 0.f, (inY1 & inX1) ? 1.f : 0.f,
                    (inY1 & inX2) ? 1.f : 0.f, (inY1 & inX3) ? 1.f : 0.f);
}

extern "C" void kernel_launch(void* const* d_in, const int* in_sizes, int n_in,
                              void* d_out, int out_size) {
    const float* boxes = (const float*)d_in[0];   // 256*4
    const float* pts   = (const float*)d_in[1];   // 256*32*2
    float* out = (float*)d_out;                   // 2 * 256*64*64
    const int B = in_sizes[0] / 4;                // 256
    float* bbox_out  = out;
    float* point_out = out + (size_t)B * MASK_N * MASK_N;
    dim3 grid(B, 2);
    zim_masks_kernel<<<grid, 256>>>(boxes, pts, bbox_out, point_out);
}